// round 9
// baseline (speedup 1.0000x reference)
#include <cuda_runtime.h>
#include <cuda_fp16.h>
#include <cstdint>
#include <math.h>

// ---------------------------------------------------------------------------
// lstm_30734785970219: z = [x|h] @ W (M=4096, K=2048, N=4096) + fused gates.
// R9: remove the 127-reg ceiling. One 512-thread CTA (BM=256, BN=128), same
// per-warp tile as R8 (32x64), 3-stage cp.async (48KB/stage), and ks-level
// fragment double-buffering (regs now allow it). fp16 mma.sync, fp32 accum.
// Gate-interleaved N (n' = 4*j + gate); fused LSTM epilogue.
// ---------------------------------------------------------------------------

static constexpr int MDIM = 4096;   // B*T
static constexpr int NDIM = 4096;   // 4*H (gate-interleaved)
static constexpr int KDIM = 2048;   // D_IN + H
static constexpr int HDIM = 1024;

static constexpr int BM = 256, BN = 128, BK = 64;
static constexpr int NCHUNK = KDIM / BK;                  // 32
static constexpr int STAGE_BYTES = (BM + BN) * BK * 2;    // 48 KB
static constexpr int B_OFF = BM * 128;                    // 32768 (B within stage)
static constexpr int SMEM_BIAS = 3 * STAGE_BYTES;         // 147456
static constexpr int SMEM_TOTAL = SMEM_BIAS + 512;        // 147968 (1 CTA/SM)
static constexpr int ZSTRIDE = 132;                       // f32 row stride (pad)

// Scratch (allocation-free rule: __device__ globals)
__device__ __half g_A[(size_t)MDIM * KDIM];
__device__ __half g_Wt[(size_t)NDIM * KDIM];
__device__ __align__(16) float g_bias[NDIM];

// ---------------------------------------------------------------------------
// helpers
// ---------------------------------------------------------------------------
__device__ __forceinline__ uint32_t smem_to_u32(const void* p) {
    uint32_t a;
    asm("{ .reg .u64 t; cvta.to.shared.u64 t, %1; cvt.u32.u64 %0, t; }"
        : "=r"(a) : "l"(p));
    return a;
}

__device__ __forceinline__ void cp_async_16(uint32_t smem, const void* gmem) {
    asm volatile("cp.async.cg.shared.global [%0], [%1], 16;"
                 :: "r"(smem), "l"(gmem));
}
#define CP_COMMIT() asm volatile("cp.async.commit_group;" ::: "memory")
#define CP_WAIT(n)  asm volatile("cp.async.wait_group %0;" :: "n"(n) : "memory")

__device__ __forceinline__ void ldmatrix_x4(uint32_t* r, uint32_t addr) {
    asm volatile("ldmatrix.sync.aligned.m8n8.x4.shared.b16 {%0,%1,%2,%3}, [%4];"
                 : "=r"(r[0]), "=r"(r[1]), "=r"(r[2]), "=r"(r[3]) : "r"(addr));
}

__device__ __forceinline__ void mma_fp16(float* d, const uint32_t* a,
                                         uint32_t b0, uint32_t b1) {
    asm volatile(
        "mma.sync.aligned.m16n8k16.row.col.f32.f16.f16.f32 "
        "{%0,%1,%2,%3}, {%4,%5,%6,%7}, {%8,%9}, {%0,%1,%2,%3};"
        : "+f"(d[0]), "+f"(d[1]), "+f"(d[2]), "+f"(d[3])
        : "r"(a[0]), "r"(a[1]), "r"(a[2]), "r"(a[3]), "r"(b0), "r"(b1));
}

// ---------------------------------------------------------------------------
// Pre-pass kernels
// ---------------------------------------------------------------------------
__global__ void pack_a_kernel(const float* __restrict__ x,
                              const float* __restrict__ h) {
    int idx = blockIdx.x * blockDim.x + threadIdx.x;    // 2,097,152 float4s
    int m = idx >> 9;
    int k = (idx & 511) << 2;
    const float* src = (k < HDIM) ? (x + (size_t)m * HDIM + k)
                                  : (h + (size_t)m * HDIM + (k - HDIM));
    float4 v = *reinterpret_cast<const float4*>(src);
    __half2* dst = reinterpret_cast<__half2*>(g_A + (size_t)m * KDIM + k);
    dst[0] = __floats2half2_rn(v.x, v.y);
    dst[1] = __floats2half2_rn(v.z, v.w);
}

// Wt[4*j+gate][k] = W_gate[k][j]  (fp16). 32x32 tiled transpose.
__global__ void transpose_w_kernel(const float* __restrict__ Wf,
                                   const float* __restrict__ Wi,
                                   const float* __restrict__ Wg,
                                   const float* __restrict__ Wo) {
    __shared__ float s[32][33];
    int gate = blockIdx.z;
    const float* W = (gate == 0) ? Wf : (gate == 1) ? Wi : (gate == 2) ? Wg : Wo;
    int j0 = blockIdx.x * 32;
    int k0 = blockIdx.y * 32;
    int tx = threadIdx.x, ty = threadIdx.y;
    #pragma unroll
    for (int kk = ty; kk < 32; kk += 8)
        s[kk][tx] = W[(size_t)(k0 + kk) * HDIM + j0 + tx];
    __syncthreads();
    #pragma unroll
    for (int jj = ty; jj < 32; jj += 8) {
        size_t r = (size_t)((j0 + jj) * 4 + gate);
        g_Wt[r * KDIM + k0 + tx] = __float2half_rn(s[tx][jj]);
    }
}

__global__ void pack_bias_kernel(const float* __restrict__ bf,
                                 const float* __restrict__ bi,
                                 const float* __restrict__ bg,
                                 const float* __restrict__ bo) {
    int j = blockIdx.x * blockDim.x + threadIdx.x;
    if (j < HDIM) {
        reinterpret_cast<float4*>(g_bias)[j] =
            make_float4(bf[j], bi[j], bg[j], bo[j]);
    }
}

// ---------------------------------------------------------------------------
// Main GEMM + fused LSTM epilogue (512 threads, 16 warps: 8(m) x 2(n))
// ---------------------------------------------------------------------------
__global__ __launch_bounds__(512, 1)
void lstm_gemm_kernel(const float* __restrict__ c_in, float* __restrict__ out) {
    extern __shared__ char smem[];
    const uint32_t smem_u32 = smem_to_u32(smem);
    const int tid = threadIdx.x;
    const int wid = tid >> 5;
    const int lane = tid & 31;
    const int warp_m = wid & 7;       // 0..7 -> 32 rows each
    const int warp_n = wid >> 3;      // 0..1 -> 64 cols each
    const int m0 = blockIdx.y * BM;
    const int r0 = blockIdx.x * BN;   // gate-interleaved column base
    const int jb = blockIdx.x * 32;   // hidden-unit base

    float* bias_s = reinterpret_cast<float*>(smem + SMEM_BIAS);
    if (tid < 128) bias_s[tid] = g_bias[r0 + tid];

    // --- cp.async producers: 4 A rows + 2 B rows per thread per stage ------
    const int ci = tid & 7;           // 16B chunk in a 128B row
    const int crow = tid >> 3;        // row base (0..63)
    const __half* pA[4];
    const __half* pB[2];
    uint32_t swA[4], swB[2];
    #pragma unroll
    for (int rep = 0; rep < 4; ++rep) {
        const int row = crow + rep * 64;
        swA[rep] = (uint32_t)(row * 128 + ((ci ^ (row & 7)) << 4));
        pA[rep] = g_A + (size_t)(m0 + row) * KDIM + ci * 8;
    }
    #pragma unroll
    for (int rep = 0; rep < 2; ++rep) {
        const int row = crow + rep * 64;
        swB[rep] = (uint32_t)(row * 128 + ((ci ^ (row & 7)) << 4));
        pB[rep] = g_Wt + (size_t)(r0 + row) * KDIM + ci * 8;
    }

    // load from current pA/pB into stage base `sm`, then advance by BK.
    auto load_stage_adv = [&](uint32_t sm) {
        #pragma unroll
        for (int rep = 0; rep < 4; ++rep) {
            cp_async_16(sm + swA[rep], pA[rep]);
            pA[rep] += BK;
        }
        #pragma unroll
        for (int rep = 0; rep < 2; ++rep) {
            cp_async_16(sm + B_OFF + swB[rep], pB[rep]);
            pB[rep] += BK;
        }
    };

    // prologue: stages 0,1 (groups #0, #1)
    load_stage_adv(smem_u32);
    CP_COMMIT();
    load_stage_adv(smem_u32 + STAGE_BYTES);
    CP_COMMIT();

    float acc[2][8][4];
    #pragma unroll
    for (int mt = 0; mt < 2; ++mt)
        #pragma unroll
        for (int nt = 0; nt < 8; ++nt)
            #pragma unroll
            for (int e = 0; e < 4; ++e) acc[mt][nt][e] = 0.0f;

    const int lrow = lane & 15;
    const int lhalf = lane >> 4;

    // Hoisted ldmatrix row offsets (swizzle XOR applies to full address:
    // stage bases are 16KB-aligned and row*128 has bits[4:6] clear).
    uint32_t rowA[2], rowB[4];
    #pragma unroll
    for (int mt = 0; mt < 2; ++mt) {
        const int row = warp_m * 32 + mt * 16 + lrow;
        rowA[mt] = (uint32_t)(row * 128 + ((row & 7) << 4));
    }
    #pragma unroll
    for (int nt2 = 0; nt2 < 4; ++nt2) {
        const int row = warp_n * 64 + nt2 * 16 + lrow;
        rowB[nt2] = (uint32_t)(row * 128 + ((row & 7) << 4));
    }

    // Rotating stage bases: sc = compute stage, sp = prefetch stage.
    uint32_t scBase = smem_u32;                      // stage 0
    uint32_t spBase = smem_u32 + 2 * STAGE_BYTES;    // stage 2
    const uint32_t smTop = smem_u32 + 2 * STAGE_BYTES;

    // Double-buffered fragments (regs are plentiful at 1 CTA/SM).
    uint32_t afr[2][2][4];   // [buf][mt][4]
    uint32_t bfr[2][4][4];   // [buf][nt2][4]

    #pragma unroll 1
    for (int c = 0; c < NCHUNK; ++c) {
        __syncthreads();               // everyone done reading slot spBase
        if (c + 2 < NCHUNK)
            load_stage_adv(spBase);
        CP_COMMIT();                   // group #(c+2); empty near tail is fine
        CP_WAIT(2);                    // group #c done -> stage sc resident
        __syncthreads();               // all threads' stage-sc parts visible

        const uint32_t smA = scBase;
        const uint32_t smB = scBase + B_OFF;

        // load fragments for ks=0 into buf 0
        {
            const uint32_t cx = (uint32_t)(lhalf << 4);
            #pragma unroll
            for (int mt = 0; mt < 2; ++mt)
                ldmatrix_x4(afr[0][mt], (smA + rowA[mt]) ^ cx);
            #pragma unroll
            for (int nt2 = 0; nt2 < 4; ++nt2)
                ldmatrix_x4(bfr[0][nt2], (smB + rowB[nt2]) ^ cx);
        }

        #pragma unroll
        for (int ks = 0; ks < 4; ++ks) {
            const int cur = ks & 1;
            if (ks < 3) {              // prefetch frags for ks+1 into other buf
                const int nxt = cur ^ 1;
                const uint32_t cx = (uint32_t)(((ks + 1) * 2 + lhalf) << 4);
                #pragma unroll
                for (int mt = 0; mt < 2; ++mt)
                    ldmatrix_x4(afr[nxt][mt], (smA + rowA[mt]) ^ cx);
                #pragma unroll
                for (int nt2 = 0; nt2 < 4; ++nt2)
                    ldmatrix_x4(bfr[nxt][nt2], (smB + rowB[nt2]) ^ cx);
            }
            #pragma unroll
            for (int mt = 0; mt < 2; ++mt)
                #pragma unroll
                for (int nt = 0; nt < 8; ++nt)
                    mma_fp16(acc[mt][nt], afr[cur][mt],
                             bfr[cur][nt >> 1][nt & 1],
                             bfr[cur][nt >> 1][(nt & 1) + 2]);
        }

        scBase = (scBase == smTop) ? smem_u32 : scBase + STAGE_BYTES;
        spBase = (spBase == smTop) ? smem_u32 : spBase + STAGE_BYTES;
    }

    // ---------------- epilogue: stage z through smem, fuse LSTM ----------------
    CP_WAIT(0);
    __syncthreads();
    float* zbuf = reinterpret_cast<float*>(smem);   // 256*132*4 = 135168 bytes
    {
        const int rb = warp_m * 32 + (lane >> 2);
        const int cb = warp_n * 64 + (lane & 3) * 2;
        #pragma unroll
        for (int mt = 0; mt < 2; ++mt)
            #pragma unroll
            for (int nt = 0; nt < 8; ++nt) {
                const int r = rb + mt * 16;
                const int cc = cb + nt * 8;
                zbuf[r * ZSTRIDE + cc]           = acc[mt][nt][0];
                zbuf[r * ZSTRIDE + cc + 1]       = acc[mt][nt][1];
                zbuf[(r + 8) * ZSTRIDE + cc]     = acc[mt][nt][2];
                zbuf[(r + 8) * ZSTRIDE + cc + 1] = acc[mt][nt][3];
            }
    }
    __syncthreads();

    {
        const int r = tid >> 1;                 // 0..255 local row
        const int jh = (tid & 1) * 16;          // 16 hidden units per thread
        const size_t m = (size_t)(m0 + r);
        const float* cin = c_in + m * HDIM + jb;
        float* hout = out + m * HDIM + jb;
        float* cout = out + (size_t)MDIM * HDIM + m * HDIM + jb;
        const float* zrow = zbuf + r * ZSTRIDE;

        #pragma unroll
        for (int q = 0; q < 4; ++q) {
            const int j0 = jh + q * 4;
            float4 ci4 = *reinterpret_cast<const float4*>(cin + j0);
            const float* cip = &ci4.x;
            float hv[4], cv[4];
            #pragma unroll
            for (int e = 0; e < 4; ++e) {
                const int j = j0 + e;
                float4 z4 = *reinterpret_cast<const float4*>(zrow + j * 4);
                float4 b4 = *reinterpret_cast<const float4*>(bias_s + j * 4);
                float zf = z4.x + b4.x, zi = z4.y + b4.y;
                float zg = z4.z + b4.z, zo = z4.w + b4.w;
                float f = 1.0f / (1.0f + __expf(-zf));
                float i = 1.0f / (1.0f + __expf(-zi));
                float g = tanhf(zg);
                float o = 1.0f / (1.0f + __expf(-zo));
                float cval = f * cip[e] + g * i;
                cv[e] = cval;
                hv[e] = tanhf(cval) * o;
            }
            *reinterpret_cast<float4*>(hout + j0) =
                make_float4(hv[0], hv[1], hv[2], hv[3]);
            *reinterpret_cast<float4*>(cout + j0) =
                make_float4(cv[0], cv[1], cv[2], cv[3]);
        }
    }
}

// ---------------------------------------------------------------------------
// kernel_launch
// ---------------------------------------------------------------------------
extern "C" void kernel_launch(void* const* d_in, const int* in_sizes, int n_in,
                              void* d_out, int out_size) {
    const float* x    = (const float*)d_in[0];
    const float* h_in = (const float*)d_in[1];
    const float* c_in = (const float*)d_in[2];
    const float* Wf   = (const float*)d_in[3];
    const float* bf   = (const float*)d_in[4];
    const float* Wi   = (const float*)d_in[5];
    const float* bi   = (const float*)d_in[6];
    const float* Wg   = (const float*)d_in[7];
    const float* bg   = (const float*)d_in[8];
    const float* Wo   = (const float*)d_in[9];
    const float* bo   = (const float*)d_in[10];
    float* out = (float*)d_out;

    pack_a_kernel<<<(MDIM * KDIM / 4) / 256, 256>>>(x, h_in);
    transpose_w_kernel<<<dim3(HDIM / 32, KDIM / 32, 4), dim3(32, 8)>>>(Wf, Wi, Wg, Wo);
    pack_bias_kernel<<<4, 256>>>(bf, bi, bg, bo);

    cudaFuncSetAttribute(lstm_gemm_kernel,
                         cudaFuncAttributeMaxDynamicSharedMemorySize, SMEM_TOTAL);
    lstm_gemm_kernel<<<dim3(NDIM / BN, MDIM / BM), 512, SMEM_TOTAL>>>(c_in, out);
}

// round 10
// speedup vs baseline: 1.2279x; 1.2279x over previous
#include <cuda_runtime.h>
#include <cuda_fp16.h>
#include <cstdint>
#include <math.h>

// ---------------------------------------------------------------------------
// lstm_30734785970219: z = [x|h] @ W (M=4096, K=2048, N=4096) + fused gates.
// R10: R8 structure (best) with ONE __syncthreads per k-chunk:
//   wait(1) -> sync -> prefetch(c+2) -> commit -> compute(c).
// 3-stage cp.async, 2 CTAs/SM (256 thr), fp16 mma.sync, fp32 accum.
// Gate-interleaved N (n' = 4*j + gate); fused LSTM epilogue.
// ---------------------------------------------------------------------------

static constexpr int MDIM = 4096;   // B*T
static constexpr int NDIM = 4096;   // 4*H (gate-interleaved)
static constexpr int KDIM = 2048;   // D_IN + H
static constexpr int HDIM = 1024;

static constexpr int BM = 128, BN = 128, BK = 64;
static constexpr int NCHUNK = KDIM / BK;                  // 32
static constexpr int STAGE_BYTES = (BM + BN) * BK * 2;    // 32 KB
static constexpr int SMEM_BIAS = 3 * STAGE_BYTES;         // 98304
static constexpr int SMEM_TOTAL = SMEM_BIAS + 512;        // 98816 -> 2 CTAs/SM
static constexpr int ZSTRIDE = 132;                       // f32 row stride (pad)

// Scratch (allocation-free rule: __device__ globals)
__device__ __half g_A[(size_t)MDIM * KDIM];
__device__ __half g_Wt[(size_t)NDIM * KDIM];
__device__ __align__(16) float g_bias[NDIM];

// ---------------------------------------------------------------------------
// helpers
// ---------------------------------------------------------------------------
__device__ __forceinline__ uint32_t smem_to_u32(const void* p) {
    uint32_t a;
    asm("{ .reg .u64 t; cvta.to.shared.u64 t, %1; cvt.u32.u64 %0, t; }"
        : "=r"(a) : "l"(p));
    return a;
}

__device__ __forceinline__ void cp_async_16(uint32_t smem, const void* gmem) {
    asm volatile("cp.async.cg.shared.global [%0], [%1], 16;"
                 :: "r"(smem), "l"(gmem));
}
#define CP_COMMIT() asm volatile("cp.async.commit_group;" ::: "memory")
#define CP_WAIT(n)  asm volatile("cp.async.wait_group %0;" :: "n"(n) : "memory")

__device__ __forceinline__ void ldmatrix_x4(uint32_t& r0, uint32_t& r1,
                                            uint32_t& r2, uint32_t& r3,
                                            uint32_t addr) {
    asm volatile("ldmatrix.sync.aligned.m8n8.x4.shared.b16 {%0,%1,%2,%3}, [%4];"
                 : "=r"(r0), "=r"(r1), "=r"(r2), "=r"(r3) : "r"(addr));
}

__device__ __forceinline__ void mma_fp16(float* d, const uint32_t* a,
                                         uint32_t b0, uint32_t b1) {
    asm volatile(
        "mma.sync.aligned.m16n8k16.row.col.f32.f16.f16.f32 "
        "{%0,%1,%2,%3}, {%4,%5,%6,%7}, {%8,%9}, {%0,%1,%2,%3};"
        : "+f"(d[0]), "+f"(d[1]), "+f"(d[2]), "+f"(d[3])
        : "r"(a[0]), "r"(a[1]), "r"(a[2]), "r"(a[3]), "r"(b0), "r"(b1));
}

// ---------------------------------------------------------------------------
// Pre-pass kernels
// ---------------------------------------------------------------------------
__global__ void pack_a_kernel(const float* __restrict__ x,
                              const float* __restrict__ h) {
    int idx = blockIdx.x * blockDim.x + threadIdx.x;    // 2,097,152 float4s
    int m = idx >> 9;
    int k = (idx & 511) << 2;
    const float* src = (k < HDIM) ? (x + (size_t)m * HDIM + k)
                                  : (h + (size_t)m * HDIM + (k - HDIM));
    float4 v = *reinterpret_cast<const float4*>(src);
    __half2* dst = reinterpret_cast<__half2*>(g_A + (size_t)m * KDIM + k);
    dst[0] = __floats2half2_rn(v.x, v.y);
    dst[1] = __floats2half2_rn(v.z, v.w);
}

// Wt[4*j+gate][k] = W_gate[k][j]  (fp16). 32x32 tiled transpose.
__global__ void transpose_w_kernel(const float* __restrict__ Wf,
                                   const float* __restrict__ Wi,
                                   const float* __restrict__ Wg,
                                   const float* __restrict__ Wo) {
    __shared__ float s[32][33];
    int gate = blockIdx.z;
    const float* W = (gate == 0) ? Wf : (gate == 1) ? Wi : (gate == 2) ? Wg : Wo;
    int j0 = blockIdx.x * 32;
    int k0 = blockIdx.y * 32;
    int tx = threadIdx.x, ty = threadIdx.y;
    #pragma unroll
    for (int kk = ty; kk < 32; kk += 8)
        s[kk][tx] = W[(size_t)(k0 + kk) * HDIM + j0 + tx];
    __syncthreads();
    #pragma unroll
    for (int jj = ty; jj < 32; jj += 8) {
        size_t r = (size_t)((j0 + jj) * 4 + gate);
        g_Wt[r * KDIM + k0 + tx] = __float2half_rn(s[tx][jj]);
    }
}

__global__ void pack_bias_kernel(const float* __restrict__ bf,
                                 const float* __restrict__ bi,
                                 const float* __restrict__ bg,
                                 const float* __restrict__ bo) {
    int j = blockIdx.x * blockDim.x + threadIdx.x;
    if (j < HDIM) {
        reinterpret_cast<float4*>(g_bias)[j] =
            make_float4(bf[j], bi[j], bg[j], bo[j]);
    }
}

// ---------------------------------------------------------------------------
// Main GEMM + fused LSTM epilogue (256 threads, 8 warps: 4(m) x 2(n))
// ---------------------------------------------------------------------------
__global__ __launch_bounds__(256, 2)
void lstm_gemm_kernel(const float* __restrict__ c_in, float* __restrict__ out) {
    extern __shared__ char smem[];
    const uint32_t smem_u32 = smem_to_u32(smem);
    const int tid = threadIdx.x;
    const int wid = tid >> 5;
    const int lane = tid & 31;
    const int warp_m = wid & 3;       // 0..3 -> 32 rows each
    const int warp_n = wid >> 2;      // 0..1 -> 64 cols each
    const int m0 = blockIdx.y * BM;
    const int r0 = blockIdx.x * BN;   // gate-interleaved column base
    const int jb = blockIdx.x * 32;   // hidden-unit base

    float* bias_s = reinterpret_cast<float*>(smem + SMEM_BIAS);
    if (tid < 128) bias_s[tid] = g_bias[r0 + tid];

    // --- cp.async producers: incrementally advanced pointers --------------
    const int ci = tid & 7;           // 16B chunk in a 128B row
    const int crb = tid >> 3;         // row base (0..31)
    const __half* pA[4];
    const __half* pB[4];
    uint32_t swoff[4];
    #pragma unroll
    for (int rep = 0; rep < 4; ++rep) {
        const int row = crb + rep * 32;
        swoff[rep] = (uint32_t)(row * 128 + ((ci ^ (row & 7)) << 4));
        pA[rep] = g_A  + (size_t)(m0 + row) * KDIM + ci * 8;
        pB[rep] = g_Wt + (size_t)(r0 + row) * KDIM + ci * 8;
    }

    // load from current pA/pB into stage base `sm`, then advance by BK.
    auto load_stage_adv = [&](uint32_t sm) {
        #pragma unroll
        for (int rep = 0; rep < 4; ++rep) {
            cp_async_16(sm + swoff[rep], pA[rep]);
            cp_async_16(sm + BM * 128 + swoff[rep], pB[rep]);
            pA[rep] += BK;
            pB[rep] += BK;
        }
    };

    // prologue: stages 0,1 (groups #0, #1)
    load_stage_adv(smem_u32);
    CP_COMMIT();
    load_stage_adv(smem_u32 + STAGE_BYTES);
    CP_COMMIT();

    float acc[2][8][4];
    #pragma unroll
    for (int mt = 0; mt < 2; ++mt)
        #pragma unroll
        for (int nt = 0; nt < 8; ++nt)
            #pragma unroll
            for (int e = 0; e < 4; ++e) acc[mt][nt][e] = 0.0f;

    const int lrow = lane & 15;
    const int lhalf = lane >> 4;

    // Hoisted ldmatrix row offsets. Stage bases are 32KB-aligned and row*128
    // has bits[4:6] clear, so the swizzle XOR applies to the full address.
    uint32_t rowA[2], rowB[4];
    #pragma unroll
    for (int mt = 0; mt < 2; ++mt) {
        const int row = warp_m * 32 + mt * 16 + lrow;
        rowA[mt] = (uint32_t)(row * 128 + ((row & 7) << 4));
    }
    #pragma unroll
    for (int nt2 = 0; nt2 < 4; ++nt2) {
        const int row = warp_n * 64 + nt2 * 16 + lrow;
        rowB[nt2] = (uint32_t)(row * 128 + ((row & 7) << 4));
    }

    // Rotating stage bases (no %3): sc = compute stage, sp = prefetch stage.
    uint32_t scBase = smem_u32;                      // stage 0
    uint32_t spBase = smem_u32 + 2 * STAGE_BYTES;    // stage 2
    const uint32_t smTop = smem_u32 + 2 * STAGE_BYTES;

    // ONE sync per chunk. Group #g carries stage g. At iter c:
    //   CP_WAIT(1): my groups up to #c complete (stage c data mine-visible).
    //   __syncthreads(): stage c globally visible; also proves every warp
    //     finished compute on stage c-1 (program order) -> its slot is free.
    //   prefetch stage c+2 into that slot; commit; compute stage c.
    #pragma unroll 1
    for (int c = 0; c < NCHUNK; ++c) {
        CP_WAIT(1);
        __syncthreads();
        if (c + 2 < NCHUNK)
            load_stage_adv(spBase);
        CP_COMMIT();                   // group #(c+2); empty near tail is fine

        const uint32_t smA = scBase;
        const uint32_t smB = scBase + BM * 128;

        #pragma unroll
        for (int ks = 0; ks < 4; ++ks) {
            const uint32_t cx = (uint32_t)((ks * 2 + lhalf) << 4);
            uint32_t a[2][4];
            #pragma unroll
            for (int mt = 0; mt < 2; ++mt)
                ldmatrix_x4(a[mt][0], a[mt][1], a[mt][2], a[mt][3],
                            (smA + rowA[mt]) ^ cx);
            uint32_t b[4][4];
            #pragma unroll
            for (int nt2 = 0; nt2 < 4; ++nt2)
                ldmatrix_x4(b[nt2][0], b[nt2][1], b[nt2][2], b[nt2][3],
                            (smB + rowB[nt2]) ^ cx);
            #pragma unroll
            for (int mt = 0; mt < 2; ++mt)
                #pragma unroll
                for (int nt = 0; nt < 8; ++nt)
                    mma_fp16(acc[mt][nt], a[mt],
                             b[nt >> 1][nt & 1], b[nt >> 1][(nt & 1) + 2]);
        }

        scBase = (scBase == smTop) ? smem_u32 : scBase + STAGE_BYTES;
        spBase = (spBase == smTop) ? smem_u32 : spBase + STAGE_BYTES;
    }

    // ---------------- epilogue: stage z through smem, fuse LSTM ----------------
    CP_WAIT(0);
    __syncthreads();
    float* zbuf = reinterpret_cast<float*>(smem);
    {
        const int rb = warp_m * 32 + (lane >> 2);
        const int cb = warp_n * 64 + (lane & 3) * 2;
        #pragma unroll
        for (int mt = 0; mt < 2; ++mt)
            #pragma unroll
            for (int nt = 0; nt < 8; ++nt) {
                const int r = rb + mt * 16;
                const int cc = cb + nt * 8;
                zbuf[r * ZSTRIDE + cc]           = acc[mt][nt][0];
                zbuf[r * ZSTRIDE + cc + 1]       = acc[mt][nt][1];
                zbuf[(r + 8) * ZSTRIDE + cc]     = acc[mt][nt][2];
                zbuf[(r + 8) * ZSTRIDE + cc + 1] = acc[mt][nt][3];
            }
    }
    __syncthreads();

    {
        const int r = tid >> 1;                 // 0..127 local row
        const int jh = (tid & 1) * 16;          // 16 hidden units per thread
        const size_t m = (size_t)(m0 + r);
        const float* cin = c_in + m * HDIM + jb;
        float* hout = out + m * HDIM + jb;
        float* cout = out + (size_t)MDIM * HDIM + m * HDIM + jb;
        const float* zrow = zbuf + r * ZSTRIDE;

        #pragma unroll
        for (int q = 0; q < 4; ++q) {
            const int j0 = jh + q * 4;
            float4 ci4 = *reinterpret_cast<const float4*>(cin + j0);
            const float* cip = &ci4.x;
            float hv[4], cv[4];
            #pragma unroll
            for (int e = 0; e < 4; ++e) {
                const int j = j0 + e;
                float4 z4 = *reinterpret_cast<const float4*>(zrow + j * 4);
                float4 b4 = *reinterpret_cast<const float4*>(bias_s + j * 4);
                float zf = z4.x + b4.x, zi = z4.y + b4.y;
                float zg = z4.z + b4.z, zo = z4.w + b4.w;
                float f = 1.0f / (1.0f + __expf(-zf));
                float i = 1.0f / (1.0f + __expf(-zi));
                float g = tanhf(zg);
                float o = 1.0f / (1.0f + __expf(-zo));
                float cval = f * cip[e] + g * i;
                cv[e] = cval;
                hv[e] = tanhf(cval) * o;
            }
            *reinterpret_cast<float4*>(hout + j0) =
                make_float4(hv[0], hv[1], hv[2], hv[3]);
            *reinterpret_cast<float4*>(cout + j0) =
                make_float4(cv[0], cv[1], cv[2], cv[3]);
        }
    }
}

// ---------------------------------------------------------------------------
// kernel_launch
// ---------------------------------------------------------------------------
extern "C" void kernel_launch(void* const* d_in, const int* in_sizes, int n_in,
                              void* d_out, int out_size) {
    const float* x    = (const float*)d_in[0];
    const float* h_in = (const float*)d_in[1];
    const float* c_in = (const float*)d_in[2];
    const float* Wf   = (const float*)d_in[3];
    const float* bf   = (const float*)d_in[4];
    const float* Wi   = (const float*)d_in[5];
    const float* bi   = (const float*)d_in[6];
    const float* Wg   = (const float*)d_in[7];
    const float* bg   = (const float*)d_in[8];
    const float* Wo   = (const float*)d_in[9];
    const float* bo   = (const float*)d_in[10];
    float* out = (float*)d_out;

    pack_a_kernel<<<(MDIM * KDIM / 4) / 256, 256>>>(x, h_in);
    transpose_w_kernel<<<dim3(HDIM / 32, KDIM / 32, 4), dim3(32, 8)>>>(Wf, Wi, Wg, Wo);
    pack_bias_kernel<<<4, 256>>>(bf, bi, bg, bo);

    cudaFuncSetAttribute(lstm_gemm_kernel,
                         cudaFuncAttributeMaxDynamicSharedMemorySize, SMEM_TOTAL);
    lstm_gemm_kernel<<<dim3(NDIM / BN, MDIM / BM), 256, SMEM_TOTAL>>>(c_in, out);
}

// round 11
// speedup vs baseline: 1.2560x; 1.0229x over previous
#include <cuda_runtime.h>
#include <cuda_fp16.h>
#include <cstdint>
#include <math.h>

// ---------------------------------------------------------------------------
// lstm_30734785970219: z = [x|h] @ W (M=4096, K=2048, N=4096) + fused gates.
// R11: register diet. Swizzle algebra (rows mod 8 invariant) compresses all
// producer/consumer addressing to single bases + immediates, freeing ~20 regs
// so ptxas (pinned at the 127-reg 2-CTA ceiling) stops emitting move bloat.
// Pipeline/tiling identical to R10 (best: 237.6us).
// ---------------------------------------------------------------------------

static constexpr int MDIM = 4096;   // B*T
static constexpr int NDIM = 4096;   // 4*H (gate-interleaved)
static constexpr int KDIM = 2048;   // D_IN + H
static constexpr int HDIM = 1024;

static constexpr int BM = 128, BN = 128, BK = 64;
static constexpr int NCHUNK = KDIM / BK;                  // 32
static constexpr int STAGE_BYTES = (BM + BN) * BK * 2;    // 32 KB
static constexpr int SMEM_BIAS = 3 * STAGE_BYTES;         // 98304
static constexpr int SMEM_TOTAL = SMEM_BIAS + 512;        // 98816 -> 2 CTAs/SM
static constexpr int ZSTRIDE = 132;                       // f32 row stride (pad)
static constexpr int ROWSTEP = 32 * KDIM;                 // 32-row stride (elems)

// Scratch (allocation-free rule: __device__ globals)
__device__ __half g_A[(size_t)MDIM * KDIM];
__device__ __half g_Wt[(size_t)NDIM * KDIM];
__device__ __align__(16) float g_bias[NDIM];

// ---------------------------------------------------------------------------
// helpers
// ---------------------------------------------------------------------------
__device__ __forceinline__ uint32_t smem_to_u32(const void* p) {
    uint32_t a;
    asm("{ .reg .u64 t; cvta.to.shared.u64 t, %1; cvt.u32.u64 %0, t; }"
        : "=r"(a) : "l"(p));
    return a;
}

__device__ __forceinline__ void cp_async_16(uint32_t smem, const void* gmem) {
    asm volatile("cp.async.cg.shared.global [%0], [%1], 16;"
                 :: "r"(smem), "l"(gmem));
}
#define CP_COMMIT() asm volatile("cp.async.commit_group;" ::: "memory")
#define CP_WAIT(n)  asm volatile("cp.async.wait_group %0;" :: "n"(n) : "memory")

__device__ __forceinline__ void ldmatrix_x4(uint32_t& r0, uint32_t& r1,
                                            uint32_t& r2, uint32_t& r3,
                                            uint32_t addr) {
    asm volatile("ldmatrix.sync.aligned.m8n8.x4.shared.b16 {%0,%1,%2,%3}, [%4];"
                 : "=r"(r0), "=r"(r1), "=r"(r2), "=r"(r3) : "r"(addr));
}

__device__ __forceinline__ void mma_fp16(float* d, const uint32_t* a,
                                         uint32_t b0, uint32_t b1) {
    asm volatile(
        "mma.sync.aligned.m16n8k16.row.col.f32.f16.f16.f32 "
        "{%0,%1,%2,%3}, {%4,%5,%6,%7}, {%8,%9}, {%0,%1,%2,%3};"
        : "+f"(d[0]), "+f"(d[1]), "+f"(d[2]), "+f"(d[3])
        : "r"(a[0]), "r"(a[1]), "r"(a[2]), "r"(a[3]), "r"(b0), "r"(b1));
}

// ---------------------------------------------------------------------------
// Pre-pass kernels
// ---------------------------------------------------------------------------
__global__ void pack_a_kernel(const float* __restrict__ x,
                              const float* __restrict__ h) {
    int idx = blockIdx.x * blockDim.x + threadIdx.x;    // 2,097,152 float4s
    int m = idx >> 9;
    int k = (idx & 511) << 2;
    const float* src = (k < HDIM) ? (x + (size_t)m * HDIM + k)
                                  : (h + (size_t)m * HDIM + (k - HDIM));
    float4 v = *reinterpret_cast<const float4*>(src);
    __half2* dst = reinterpret_cast<__half2*>(g_A + (size_t)m * KDIM + k);
    dst[0] = __floats2half2_rn(v.x, v.y);
    dst[1] = __floats2half2_rn(v.z, v.w);
}

// Wt[4*j+gate][k] = W_gate[k][j]  (fp16). 32x32 tiled transpose.
__global__ void transpose_w_kernel(const float* __restrict__ Wf,
                                   const float* __restrict__ Wi,
                                   const float* __restrict__ Wg,
                                   const float* __restrict__ Wo) {
    __shared__ float s[32][33];
    int gate = blockIdx.z;
    const float* W = (gate == 0) ? Wf : (gate == 1) ? Wi : (gate == 2) ? Wg : Wo;
    int j0 = blockIdx.x * 32;
    int k0 = blockIdx.y * 32;
    int tx = threadIdx.x, ty = threadIdx.y;
    #pragma unroll
    for (int kk = ty; kk < 32; kk += 8)
        s[kk][tx] = W[(size_t)(k0 + kk) * HDIM + j0 + tx];
    __syncthreads();
    #pragma unroll
    for (int jj = ty; jj < 32; jj += 8) {
        size_t r = (size_t)((j0 + jj) * 4 + gate);
        g_Wt[r * KDIM + k0 + tx] = __float2half_rn(s[tx][jj]);
    }
}

__global__ void pack_bias_kernel(const float* __restrict__ bf,
                                 const float* __restrict__ bi,
                                 const float* __restrict__ bg,
                                 const float* __restrict__ bo) {
    int j = blockIdx.x * blockDim.x + threadIdx.x;
    if (j < HDIM) {
        reinterpret_cast<float4*>(g_bias)[j] =
            make_float4(bf[j], bi[j], bg[j], bo[j]);
    }
}

// ---------------------------------------------------------------------------
// Main GEMM + fused LSTM epilogue (256 threads, 8 warps: 4(m) x 2(n))
// ---------------------------------------------------------------------------
__global__ __launch_bounds__(256, 2)
void lstm_gemm_kernel(const float* __restrict__ c_in, float* __restrict__ out) {
    extern __shared__ char smem[];
    const uint32_t smem_u32 = smem_to_u32(smem);
    const int tid = threadIdx.x;
    const int wid = tid >> 5;
    const int lane = tid & 31;
    const int warp_m = wid & 3;       // 0..3 -> 32 rows each
    const int warp_n = wid >> 2;      // 0..1 -> 64 cols each
    const int m0 = blockIdx.y * BM;
    const int r0 = blockIdx.x * BN;   // gate-interleaved column base
    const int jb = blockIdx.x * 32;   // hidden-unit base

    float* bias_s = reinterpret_cast<float*>(smem + SMEM_BIAS);
    if (tid < 128) bias_s[tid] = g_bias[r0 + tid];

    // --- producers: single base pointer + compile-time strides -------------
    // Rows rep*32 apart share the swizzle term (32 % 8 == 0):
    //   swoff[rep] = sw0 + rep*4096,  pX[rep] = pX0 + rep*ROWSTEP.
    const int ci = tid & 7;           // 16B chunk in a 128B row
    const int crb = tid >> 3;         // row base (0..31)
    const uint32_t sw0 = (uint32_t)(crb * 128 + ((ci ^ (crb & 7)) << 4));
    const __half* pA0 = g_A  + (size_t)(m0 + crb) * KDIM + ci * 8;
    const __half* pB0 = g_Wt + (size_t)(r0 + crb) * KDIM + ci * 8;

    // load from current pA0/pB0 into stage base `sm`, then advance by BK.
    auto load_stage_adv = [&](uint32_t sm) {
        const uint32_t s0 = sm + sw0;
        #pragma unroll
        for (int rep = 0; rep < 4; ++rep)
            cp_async_16(s0 + rep * 4096, pA0 + rep * ROWSTEP);
        #pragma unroll
        for (int rep = 0; rep < 4; ++rep)
            cp_async_16(s0 + BM * 128 + rep * 4096, pB0 + rep * ROWSTEP);
        pA0 += BK;
        pB0 += BK;
    };

    // prologue: stages 0,1 (groups #0, #1)
    load_stage_adv(smem_u32);
    CP_COMMIT();
    load_stage_adv(smem_u32 + STAGE_BYTES);
    CP_COMMIT();

    float acc[2][8][4];
    #pragma unroll
    for (int mt = 0; mt < 2; ++mt)
        #pragma unroll
        for (int nt = 0; nt < 8; ++nt)
            #pragma unroll
            for (int e = 0; e < 4; ++e) acc[mt][nt][e] = 0.0f;

    const int lrow = lane & 15;
    const int lhalf = lane >> 4;

    // Single ldmatrix row base per matrix; mt/nt2 steps of 16 rows preserve
    // row&7, so higher fragments are +2048 immediates after the swizzle XOR.
    const int arow = warp_m * 32 + lrow;
    const int brow = warp_n * 64 + lrow;
    const uint32_t rA0 = (uint32_t)(arow * 128 + ((arow & 7) << 4));
    const uint32_t rB0 = (uint32_t)(brow * 128 + ((brow & 7) << 4));

    // Rotating stage bases: sc = compute stage, sp = prefetch stage.
    uint32_t scBase = smem_u32;                      // stage 0
    uint32_t spBase = smem_u32 + 2 * STAGE_BYTES;    // stage 2
    const uint32_t smTop = smem_u32 + 2 * STAGE_BYTES;

    // One sync per chunk: wait(1) -> sync -> prefetch(c+2) -> compute(c).
    #pragma unroll 1
    for (int c = 0; c < NCHUNK; ++c) {
        CP_WAIT(1);
        __syncthreads();
        if (c + 2 < NCHUNK)
            load_stage_adv(spBase);
        CP_COMMIT();                   // group #(c+2); empty near tail is fine

        const uint32_t aBase = scBase + rA0;
        const uint32_t bBase = scBase + BM * 128 + rB0;

        #pragma unroll
        for (int ks = 0; ks < 4; ++ks) {
            const uint32_t cx = (uint32_t)((ks * 2 + lhalf) << 4);
            const uint32_t a0 = aBase ^ cx;
            const uint32_t b0 = bBase ^ cx;
            uint32_t a[2][4];
            ldmatrix_x4(a[0][0], a[0][1], a[0][2], a[0][3], a0);
            ldmatrix_x4(a[1][0], a[1][1], a[1][2], a[1][3], a0 + 2048);
            uint32_t b[4][4];
            ldmatrix_x4(b[0][0], b[0][1], b[0][2], b[0][3], b0);
            ldmatrix_x4(b[1][0], b[1][1], b[1][2], b[1][3], b0 + 2048);
            ldmatrix_x4(b[2][0], b[2][1], b[2][2], b[2][3], b0 + 4096);
            ldmatrix_x4(b[3][0], b[3][1], b[3][2], b[3][3], b0 + 6144);
            #pragma unroll
            for (int mt = 0; mt < 2; ++mt)
                #pragma unroll
                for (int nt = 0; nt < 8; ++nt)
                    mma_fp16(acc[mt][nt], a[mt],
                             b[nt >> 1][nt & 1], b[nt >> 1][(nt & 1) + 2]);
        }

        scBase = (scBase == smTop) ? smem_u32 : scBase + STAGE_BYTES;
        spBase = (spBase == smTop) ? smem_u32 : spBase + STAGE_BYTES;
    }

    // ---------------- epilogue: stage z through smem, fuse LSTM ----------------
    CP_WAIT(0);
    __syncthreads();
    float* zbuf = reinterpret_cast<float*>(smem);
    {
        const int rb = warp_m * 32 + (lane >> 2);
        const int cb = warp_n * 64 + (lane & 3) * 2;
        #pragma unroll
        for (int mt = 0; mt < 2; ++mt)
            #pragma unroll
            for (int nt = 0; nt < 8; ++nt) {
                const int r = rb + mt * 16;
                const int cc = cb + nt * 8;
                zbuf[r * ZSTRIDE + cc]           = acc[mt][nt][0];
                zbuf[r * ZSTRIDE + cc + 1]       = acc[mt][nt][1];
                zbuf[(r + 8) * ZSTRIDE + cc]     = acc[mt][nt][2];
                zbuf[(r + 8) * ZSTRIDE + cc + 1] = acc[mt][nt][3];
            }
    }
    __syncthreads();

    {
        const int r = tid >> 1;                 // 0..127 local row
        const int jh = (tid & 1) * 16;          // 16 hidden units per thread
        const size_t m = (size_t)(m0 + r);
        const float* cin = c_in + m * HDIM + jb;
        float* hout = out + m * HDIM + jb;
        float* cout = out + (size_t)MDIM * HDIM + m * HDIM + jb;
        const float* zrow = zbuf + r * ZSTRIDE;

        #pragma unroll
        for (int q = 0; q < 4; ++q) {
            const int j0 = jh + q * 4;
            float4 ci4 = *reinterpret_cast<const float4*>(cin + j0);
            const float* cip = &ci4.x;
            float hv[4], cv[4];
            #pragma unroll
            for (int e = 0; e < 4; ++e) {
                const int j = j0 + e;
                float4 z4 = *reinterpret_cast<const float4*>(zrow + j * 4);
                float4 b4 = *reinterpret_cast<const float4*>(bias_s + j * 4);
                float zf = z4.x + b4.x, zi = z4.y + b4.y;
                float zg = z4.z + b4.z, zo = z4.w + b4.w;
                float f = 1.0f / (1.0f + __expf(-zf));
                float i = 1.0f / (1.0f + __expf(-zi));
                float g = tanhf(zg);
                float o = 1.0f / (1.0f + __expf(-zo));
                float cval = f * cip[e] + g * i;
                cv[e] = cval;
                hv[e] = tanhf(cval) * o;
            }
            *reinterpret_cast<float4*>(hout + j0) =
                make_float4(hv[0], hv[1], hv[2], hv[3]);
            *reinterpret_cast<float4*>(cout + j0) =
                make_float4(cv[0], cv[1], cv[2], cv[3]);
        }
    }
}

// ---------------------------------------------------------------------------
// kernel_launch
// ---------------------------------------------------------------------------
extern "C" void kernel_launch(void* const* d_in, const int* in_sizes, int n_in,
                              void* d_out, int out_size) {
    const float* x    = (const float*)d_in[0];
    const float* h_in = (const float*)d_in[1];
    const float* c_in = (const float*)d_in[2];
    const float* Wf   = (const float*)d_in[3];
    const float* bf   = (const float*)d_in[4];
    const float* Wi   = (const float*)d_in[5];
    const float* bi   = (const float*)d_in[6];
    const float* Wg   = (const float*)d_in[7];
    const float* bg   = (const float*)d_in[8];
    const float* Wo   = (const float*)d_in[9];
    const float* bo   = (const float*)d_in[10];
    float* out = (float*)d_out;

    pack_a_kernel<<<(MDIM * KDIM / 4) / 256, 256>>>(x, h_in);
    transpose_w_kernel<<<dim3(HDIM / 32, KDIM / 32, 4), dim3(32, 8)>>>(Wf, Wi, Wg, Wo);
    pack_bias_kernel<<<4, 256>>>(bf, bi, bg, bo);

    cudaFuncSetAttribute(lstm_gemm_kernel,
                         cudaFuncAttributeMaxDynamicSharedMemorySize, SMEM_TOTAL);
    lstm_gemm_kernel<<<dim3(NDIM / BN, MDIM / BM), 256, SMEM_TOTAL>>>(c_in, out);
}

// round 13
// speedup vs baseline: 1.3066x; 1.0403x over previous
#include <cuda_runtime.h>
#include <cuda_fp16.h>
#include <cstdint>
#include <math.h>

// ---------------------------------------------------------------------------
// lstm_30734785970219: z = [x|h] @ W (M=4096, K=2048, N=4096) + fused gates.
// R12 resubmit (R12 bench = container-acquisition infra failure, no signal).
// Pre-pass overhaul (GEMM loop identical to R11 best: GEMM 199.6us):
//  - transpose_w: coalesced float4 reads + 32B/thread coalesced fp16 stores
//    (old version did scattered 2B stores), bias packing fused in.
//  - pack_a: 8 floats/thread, single 16B store.
// fp16 mma.sync, fp32 accum, 2 CTAs/SM, gate-interleaved N.
// ---------------------------------------------------------------------------

static constexpr int MDIM = 4096;   // B*T
static constexpr int NDIM = 4096;   // 4*H (gate-interleaved)
static constexpr int KDIM = 2048;   // D_IN + H
static constexpr int HDIM = 1024;

static constexpr int BM = 128, BN = 128, BK = 64;
static constexpr int NCHUNK = KDIM / BK;                  // 32
static constexpr int STAGE_BYTES = (BM + BN) * BK * 2;    // 32 KB
static constexpr int SMEM_BIAS = 3 * STAGE_BYTES;         // 98304
static constexpr int SMEM_TOTAL = SMEM_BIAS + 512;        // 98816 -> 2 CTAs/SM
static constexpr int ZSTRIDE = 132;                       // f32 row stride (pad)
static constexpr int ROWSTEP = 32 * KDIM;                 // 32-row stride (elems)

// Scratch (allocation-free rule: __device__ globals)
__device__ __half g_A[(size_t)MDIM * KDIM];
__device__ __half g_Wt[(size_t)NDIM * KDIM];
__device__ __align__(16) float g_bias[NDIM];

// ---------------------------------------------------------------------------
// helpers
// ---------------------------------------------------------------------------
__device__ __forceinline__ uint32_t smem_to_u32(const void* p) {
    uint32_t a;
    asm("{ .reg .u64 t; cvta.to.shared.u64 t, %1; cvt.u32.u64 %0, t; }"
        : "=r"(a) : "l"(p));
    return a;
}

__device__ __forceinline__ void cp_async_16(uint32_t smem, const void* gmem) {
    asm volatile("cp.async.cg.shared.global [%0], [%1], 16;"
                 :: "r"(smem), "l"(gmem));
}
#define CP_COMMIT() asm volatile("cp.async.commit_group;" ::: "memory")
#define CP_WAIT(n)  asm volatile("cp.async.wait_group %0;" :: "n"(n) : "memory")

__device__ __forceinline__ void ldmatrix_x4(uint32_t& r0, uint32_t& r1,
                                            uint32_t& r2, uint32_t& r3,
                                            uint32_t addr) {
    asm volatile("ldmatrix.sync.aligned.m8n8.x4.shared.b16 {%0,%1,%2,%3}, [%4];"
                 : "=r"(r0), "=r"(r1), "=r"(r2), "=r"(r3) : "r"(addr));
}

__device__ __forceinline__ void mma_fp16(float* d, const uint32_t* a,
                                         uint32_t b0, uint32_t b1) {
    asm volatile(
        "mma.sync.aligned.m16n8k16.row.col.f32.f16.f16.f32 "
        "{%0,%1,%2,%3}, {%4,%5,%6,%7}, {%8,%9}, {%0,%1,%2,%3};"
        : "+f"(d[0]), "+f"(d[1]), "+f"(d[2]), "+f"(d[3])
        : "r"(a[0]), "r"(a[1]), "r"(a[2]), "r"(a[3]), "r"(b0), "r"(b1));
}

// ---------------------------------------------------------------------------
// Pre-pass kernels
// ---------------------------------------------------------------------------

// A[m][k] = k < 1024 ? x : h, fp16. 8 floats per thread, one 16B store.
__global__ void pack_a_kernel(const float* __restrict__ x,
                              const float* __restrict__ h) {
    int idx = blockIdx.x * blockDim.x + threadIdx.x;    // 1,048,576 iters
    int m = idx >> 8;
    int k = (idx & 255) << 3;        // 8-float chunks never straddle k=1024
    const float* src = (k < HDIM) ? (x + (size_t)m * HDIM + k)
                                  : (h + (size_t)m * HDIM + (k - HDIM));
    float4 v0 = *reinterpret_cast<const float4*>(src);
    float4 v1 = *reinterpret_cast<const float4*>(src + 4);
    __half2 o[4];
    o[0] = __floats2half2_rn(v0.x, v0.y);
    o[1] = __floats2half2_rn(v0.z, v0.w);
    o[2] = __floats2half2_rn(v1.x, v1.y);
    o[3] = __floats2half2_rn(v1.z, v1.w);
    *reinterpret_cast<uint4*>(g_A + (size_t)m * KDIM + k) =
        *reinterpret_cast<const uint4*>(o);
}

// Wt[4*j+gate][k] = W_gate[k][j], fp16, coalesced both ways via smem.
// Block: 32 j-values x 128 k-values for one gate. Bias fused (by == 0).
__global__ void transpose_w_kernel(const float* __restrict__ Wf,
                                   const float* __restrict__ Wi,
                                   const float* __restrict__ Wg,
                                   const float* __restrict__ Wo,
                                   const float* __restrict__ bf,
                                   const float* __restrict__ bi,
                                   const float* __restrict__ bg,
                                   const float* __restrict__ bo) {
    __shared__ float s[32][133];     // [j][k], padded
    const int gate = blockIdx.z;
    const float* W = (gate == 0) ? Wf : (gate == 1) ? Wi : (gate == 2) ? Wg : Wo;
    const int j0 = blockIdx.x * 32;
    const int k0 = blockIdx.y * 128;
    const int t = threadIdx.x;       // 256 threads

    // Load: rows = k (coalesced float4 along j).
    const int jc = (t & 7) << 2;     // j offset 0,4,...,28
    const int kr = t >> 3;           // 0..31
    #pragma unroll
    for (int it = 0; it < 4; ++it) {
        const int k = kr + it * 32;
        float4 v = *reinterpret_cast<const float4*>(
            W + (size_t)(k0 + k) * HDIM + j0 + jc);
        s[jc + 0][k] = v.x;
        s[jc + 1][k] = v.y;
        s[jc + 2][k] = v.z;
        s[jc + 3][k] = v.w;
    }
    __syncthreads();

    // Store: row r = 4*(j0+jj)+gate, 16 consecutive k as fp16 (32B/thread).
    const int jj = t >> 3;           // 0..31
    const int kc = (t & 7) << 4;     // 0,16,...,112
    __half2 o[8];
    #pragma unroll
    for (int e = 0; e < 8; ++e)
        o[e] = __floats2half2_rn(s[jj][kc + 2 * e], s[jj][kc + 2 * e + 1]);
    __half* dst = g_Wt + (size_t)((j0 + jj) * 4 + gate) * KDIM + k0 + kc;
    reinterpret_cast<uint4*>(dst)[0] = reinterpret_cast<const uint4*>(o)[0];
    reinterpret_cast<uint4*>(dst)[1] = reinterpret_cast<const uint4*>(o)[1];

    // Bias: once per (j0, gate).
    if (blockIdx.y == 0 && t < 32) {
        const float* b = (gate == 0) ? bf : (gate == 1) ? bi
                        : (gate == 2) ? bg : bo;
        g_bias[(j0 + t) * 4 + gate] = b[j0 + t];
    }
}

// ---------------------------------------------------------------------------
// Main GEMM + fused LSTM epilogue (256 threads, 8 warps: 4(m) x 2(n))
// Identical to R11.
// ---------------------------------------------------------------------------
__global__ __launch_bounds__(256, 2)
void lstm_gemm_kernel(const float* __restrict__ c_in, float* __restrict__ out) {
    extern __shared__ char smem[];
    const uint32_t smem_u32 = smem_to_u32(smem);
    const int tid = threadIdx.x;
    const int wid = tid >> 5;
    const int lane = tid & 31;
    const int warp_m = wid & 3;       // 0..3 -> 32 rows each
    const int warp_n = wid >> 2;      // 0..1 -> 64 cols each
    const int m0 = blockIdx.y * BM;
    const int r0 = blockIdx.x * BN;   // gate-interleaved column base
    const int jb = blockIdx.x * 32;   // hidden-unit base

    float* bias_s = reinterpret_cast<float*>(smem + SMEM_BIAS);
    if (tid < 128) bias_s[tid] = g_bias[r0 + tid];

    // --- producers: single base pointer + compile-time strides -------------
    const int ci = tid & 7;           // 16B chunk in a 128B row
    const int crb = tid >> 3;         // row base (0..31)
    const uint32_t sw0 = (uint32_t)(crb * 128 + ((ci ^ (crb & 7)) << 4));
    const __half* pA0 = g_A  + (size_t)(m0 + crb) * KDIM + ci * 8;
    const __half* pB0 = g_Wt + (size_t)(r0 + crb) * KDIM + ci * 8;

    auto load_stage_adv = [&](uint32_t sm) {
        const uint32_t s0 = sm + sw0;
        #pragma unroll
        for (int rep = 0; rep < 4; ++rep)
            cp_async_16(s0 + rep * 4096, pA0 + rep * ROWSTEP);
        #pragma unroll
        for (int rep = 0; rep < 4; ++rep)
            cp_async_16(s0 + BM * 128 + rep * 4096, pB0 + rep * ROWSTEP);
        pA0 += BK;
        pB0 += BK;
    };

    // prologue: stages 0,1 (groups #0, #1)
    load_stage_adv(smem_u32);
    CP_COMMIT();
    load_stage_adv(smem_u32 + STAGE_BYTES);
    CP_COMMIT();

    float acc[2][8][4];
    #pragma unroll
    for (int mt = 0; mt < 2; ++mt)
        #pragma unroll
        for (int nt = 0; nt < 8; ++nt)
            #pragma unroll
            for (int e = 0; e < 4; ++e) acc[mt][nt][e] = 0.0f;

    const int lrow = lane & 15;
    const int lhalf = lane >> 4;

    const int arow = warp_m * 32 + lrow;
    const int brow = warp_n * 64 + lrow;
    const uint32_t rA0 = (uint32_t)(arow * 128 + ((arow & 7) << 4));
    const uint32_t rB0 = (uint32_t)(brow * 128 + ((brow & 7) << 4));

    uint32_t scBase = smem_u32;                      // stage 0
    uint32_t spBase = smem_u32 + 2 * STAGE_BYTES;    // stage 2
    const uint32_t smTop = smem_u32 + 2 * STAGE_BYTES;

    #pragma unroll 1
    for (int c = 0; c < NCHUNK; ++c) {
        CP_WAIT(1);
        __syncthreads();
        if (c + 2 < NCHUNK)
            load_stage_adv(spBase);
        CP_COMMIT();

        const uint32_t aBase = scBase + rA0;
        const uint32_t bBase = scBase + BM * 128 + rB0;

        #pragma unroll
        for (int ks = 0; ks < 4; ++ks) {
            const uint32_t cx = (uint32_t)((ks * 2 + lhalf) << 4);
            const uint32_t a0 = aBase ^ cx;
            const uint32_t b0 = bBase ^ cx;
            uint32_t a[2][4];
            ldmatrix_x4(a[0][0], a[0][1], a[0][2], a[0][3], a0);
            ldmatrix_x4(a[1][0], a[1][1], a[1][2], a[1][3], a0 + 2048);
            uint32_t b[4][4];
            ldmatrix_x4(b[0][0], b[0][1], b[0][2], b[0][3], b0);
            ldmatrix_x4(b[1][0], b[1][1], b[1][2], b[1][3], b0 + 2048);
            ldmatrix_x4(b[2][0], b[2][1], b[2][2], b[2][3], b0 + 4096);
            ldmatrix_x4(b[3][0], b[3][1], b[3][2], b[3][3], b0 + 6144);
            #pragma unroll
            for (int mt = 0; mt < 2; ++mt)
                #pragma unroll
                for (int nt = 0; nt < 8; ++nt)
                    mma_fp16(acc[mt][nt], a[mt],
                             b[nt >> 1][nt & 1], b[nt >> 1][(nt & 1) + 2]);
        }

        scBase = (scBase == smTop) ? smem_u32 : scBase + STAGE_BYTES;
        spBase = (spBase == smTop) ? smem_u32 : spBase + STAGE_BYTES;
    }

    // ---------------- epilogue: stage z through smem, fuse LSTM ----------------
    CP_WAIT(0);
    __syncthreads();
    float* zbuf = reinterpret_cast<float*>(smem);
    {
        const int rb = warp_m * 32 + (lane >> 2);
        const int cb = warp_n * 64 + (lane & 3) * 2;
        #pragma unroll
        for (int mt = 0; mt < 2; ++mt)
            #pragma unroll
            for (int nt = 0; nt < 8; ++nt) {
                const int r = rb + mt * 16;
                const int cc = cb + nt * 8;
                zbuf[r * ZSTRIDE + cc]           = acc[mt][nt][0];
                zbuf[r * ZSTRIDE + cc + 1]       = acc[mt][nt][1];
                zbuf[(r + 8) * ZSTRIDE + cc]     = acc[mt][nt][2];
                zbuf[(r + 8) * ZSTRIDE + cc + 1] = acc[mt][nt][3];
            }
    }
    __syncthreads();

    {
        const int r = tid >> 1;                 // 0..127 local row
        const int jh = (tid & 1) * 16;          // 16 hidden units per thread
        const size_t m = (size_t)(m0 + r);
        const float* cin = c_in + m * HDIM + jb;
        float* hout = out + m * HDIM + jb;
        float* cout = out + (size_t)MDIM * HDIM + m * HDIM + jb;
        const float* zrow = zbuf + r * ZSTRIDE;

        #pragma unroll
        for (int q = 0; q < 4; ++q) {
            const int j0 = jh + q * 4;
            float4 ci4 = *reinterpret_cast<const float4*>(cin + j0);
            const float* cip = &ci4.x;
            float hv[4], cv[4];
            #pragma unroll
            for (int e = 0; e < 4; ++e) {
                const int j = j0 + e;
                float4 z4 = *reinterpret_cast<const float4*>(zrow + j * 4);
                float4 b4 = *reinterpret_cast<const float4*>(bias_s + j * 4);
                float zf = z4.x + b4.x, zi = z4.y + b4.y;
                float zg = z4.z + b4.z, zo = z4.w + b4.w;
                float f = 1.0f / (1.0f + __expf(-zf));
                float i = 1.0f / (1.0f + __expf(-zi));
                float g = tanhf(zg);
                float o = 1.0f / (1.0f + __expf(-zo));
                float cval = f * cip[e] + g * i;
                cv[e] = cval;
                hv[e] = tanhf(cval) * o;
            }
            *reinterpret_cast<float4*>(hout + j0) =
                make_float4(hv[0], hv[1], hv[2], hv[3]);
            *reinterpret_cast<float4*>(cout + j0) =
                make_float4(cv[0], cv[1], cv[2], cv[3]);
        }
    }
}

// ---------------------------------------------------------------------------
// kernel_launch
// ---------------------------------------------------------------------------
extern "C" void kernel_launch(void* const* d_in, const int* in_sizes, int n_in,
                              void* d_out, int out_size) {
    const float* x    = (const float*)d_in[0];
    const float* h_in = (const float*)d_in[1];
    const float* c_in = (const float*)d_in[2];
    const float* Wf   = (const float*)d_in[3];
    const float* bf   = (const float*)d_in[4];
    const float* Wi   = (const float*)d_in[5];
    const float* bi   = (const float*)d_in[6];
    const float* Wg   = (const float*)d_in[7];
    const float* bg   = (const float*)d_in[8];
    const float* Wo   = (const float*)d_in[9];
    const float* bo   = (const float*)d_in[10];
    float* out = (float*)d_out;

    pack_a_kernel<<<(MDIM * KDIM / 8) / 256, 256>>>(x, h_in);
    transpose_w_kernel<<<dim3(HDIM / 32, KDIM / 128, 4), 256>>>(
        Wf, Wi, Wg, Wo, bf, bi, bg, bo);

    cudaFuncSetAttribute(lstm_gemm_kernel,
                         cudaFuncAttributeMaxDynamicSharedMemorySize, SMEM_TOTAL);
    lstm_gemm_kernel<<<dim3(NDIM / BN, MDIM / BM), 256, SMEM_TOTAL>>>(c_in, out);
}

// round 14
// speedup vs baseline: 1.3318x; 1.0193x over previous
#include <cuda_runtime.h>
#include <cuda_fp16.h>
#include <cstdint>
#include <math.h>

// ---------------------------------------------------------------------------
// lstm_30734785970219: z = [x|h] @ W (M=4096, K=2048, N=4096) + fused gates.
// R14: (GEMM loop byte-identical to R13 best, GEMM ~199.6us)
//  - pre-passes merged into ONE kernel launch (grid branch).
//  - epilogue fast math: __fdividef sigmoid, exp-based tanh (saturating).
// fp16 mma.sync, fp32 accum, 2 CTAs/SM, gate-interleaved N.
// ---------------------------------------------------------------------------

static constexpr int MDIM = 4096;   // B*T
static constexpr int NDIM = 4096;   // 4*H (gate-interleaved)
static constexpr int KDIM = 2048;   // D_IN + H
static constexpr int HDIM = 1024;

static constexpr int BM = 128, BN = 128, BK = 64;
static constexpr int NCHUNK = KDIM / BK;                  // 32
static constexpr int STAGE_BYTES = (BM + BN) * BK * 2;    // 32 KB
static constexpr int SMEM_BIAS = 3 * STAGE_BYTES;         // 98304
static constexpr int SMEM_TOTAL = SMEM_BIAS + 512;        // 98816 -> 2 CTAs/SM
static constexpr int ZSTRIDE = 132;                       // f32 row stride (pad)
static constexpr int ROWSTEP = 32 * KDIM;                 // 32-row stride (elems)

static constexpr int PACKA_BLOCKS = MDIM * KDIM / 8 / 256;     // 4096
static constexpr int TRANS_BLOCKS_X = HDIM / 32;               // 32
static constexpr int TRANS_BLOCKS_Y = KDIM / 128;              // 16
static constexpr int PREP_BLOCKS = PACKA_BLOCKS + TRANS_BLOCKS_X * TRANS_BLOCKS_Y * 4;

// Scratch (allocation-free rule: __device__ globals)
__device__ __half g_A[(size_t)MDIM * KDIM];
__device__ __half g_Wt[(size_t)NDIM * KDIM];
__device__ __align__(16) float g_bias[NDIM];

// ---------------------------------------------------------------------------
// helpers
// ---------------------------------------------------------------------------
__device__ __forceinline__ uint32_t smem_to_u32(const void* p) {
    uint32_t a;
    asm("{ .reg .u64 t; cvta.to.shared.u64 t, %1; cvt.u32.u64 %0, t; }"
        : "=r"(a) : "l"(p));
    return a;
}

__device__ __forceinline__ void cp_async_16(uint32_t smem, const void* gmem) {
    asm volatile("cp.async.cg.shared.global [%0], [%1], 16;"
                 :: "r"(smem), "l"(gmem));
}
#define CP_COMMIT() asm volatile("cp.async.commit_group;" ::: "memory")
#define CP_WAIT(n)  asm volatile("cp.async.wait_group %0;" :: "n"(n) : "memory")

__device__ __forceinline__ void ldmatrix_x4(uint32_t& r0, uint32_t& r1,
                                            uint32_t& r2, uint32_t& r3,
                                            uint32_t addr) {
    asm volatile("ldmatrix.sync.aligned.m8n8.x4.shared.b16 {%0,%1,%2,%3}, [%4];"
                 : "=r"(r0), "=r"(r1), "=r"(r2), "=r"(r3) : "r"(addr));
}

__device__ __forceinline__ void mma_fp16(float* d, const uint32_t* a,
                                         uint32_t b0, uint32_t b1) {
    asm volatile(
        "mma.sync.aligned.m16n8k16.row.col.f32.f16.f16.f32 "
        "{%0,%1,%2,%3}, {%4,%5,%6,%7}, {%8,%9}, {%0,%1,%2,%3};"
        : "+f"(d[0]), "+f"(d[1]), "+f"(d[2]), "+f"(d[3])
        : "r"(a[0]), "r"(a[1]), "r"(a[2]), "r"(a[3]), "r"(b0), "r"(b1));
}

// Fast sigmoid / tanh (MUFU-based; saturate correctly at +/-inf).
__device__ __forceinline__ float fast_sigmoid(float x) {
    return __fdividef(1.0f, 1.0f + __expf(-x));
}
__device__ __forceinline__ float fast_tanh(float x) {
    return 1.0f - __fdividef(2.0f, __expf(2.0f * x) + 1.0f);
}

// ---------------------------------------------------------------------------
// Merged pre-pass kernel: blocks [0, 4096) pack A; rest transpose W + bias.
// ---------------------------------------------------------------------------
__global__ void prep_kernel(const float* __restrict__ x,
                            const float* __restrict__ h,
                            const float* __restrict__ Wf,
                            const float* __restrict__ Wi,
                            const float* __restrict__ Wg,
                            const float* __restrict__ Wo,
                            const float* __restrict__ bf,
                            const float* __restrict__ bi,
                            const float* __restrict__ bg,
                            const float* __restrict__ bo) {
    __shared__ float s[32][133];     // transpose staging (unused by pack-A)
    const int t = threadIdx.x;       // 256 threads

    if (blockIdx.x < PACKA_BLOCKS) {
        // ---- pack A: A[m][k] = k<1024 ? x : h, fp16, 8 floats/thread ----
        int idx = blockIdx.x * 256 + t;
        int m = idx >> 8;
        int k = (idx & 255) << 3;    // never straddles k=1024
        const float* src = (k < HDIM) ? (x + (size_t)m * HDIM + k)
                                      : (h + (size_t)m * HDIM + (k - HDIM));
        float4 v0 = *reinterpret_cast<const float4*>(src);
        float4 v1 = *reinterpret_cast<const float4*>(src + 4);
        __half2 o[4];
        o[0] = __floats2half2_rn(v0.x, v0.y);
        o[1] = __floats2half2_rn(v0.z, v0.w);
        o[2] = __floats2half2_rn(v1.x, v1.y);
        o[3] = __floats2half2_rn(v1.z, v1.w);
        *reinterpret_cast<uint4*>(g_A + (size_t)m * KDIM + k) =
            *reinterpret_cast<const uint4*>(o);
        return;
    }

    // ---- transpose W: Wt[4*j+gate][k] = W_gate[k][j], fp16 ----
    const int bb = blockIdx.x - PACKA_BLOCKS;            // 0..2047
    const int gate = bb >> 9;                            // /512
    const int rem = bb & 511;
    const int bx = rem & (TRANS_BLOCKS_X - 1);           // j tile (32)
    const int by = rem >> 5;                             // k tile (16)
    const float* W = (gate == 0) ? Wf : (gate == 1) ? Wi : (gate == 2) ? Wg : Wo;
    const int j0 = bx * 32;
    const int k0 = by * 128;

    const int jc = (t & 7) << 2;     // j offset 0,4,...,28
    const int kr = t >> 3;           // 0..31
    #pragma unroll
    for (int it = 0; it < 4; ++it) {
        const int k = kr + it * 32;
        float4 v = *reinterpret_cast<const float4*>(
            W + (size_t)(k0 + k) * HDIM + j0 + jc);
        s[jc + 0][k] = v.x;
        s[jc + 1][k] = v.y;
        s[jc + 2][k] = v.z;
        s[jc + 3][k] = v.w;
    }
    __syncthreads();

    const int jj = t >> 3;           // 0..31
    const int kc = (t & 7) << 4;     // 0,16,...,112
    __half2 o[8];
    #pragma unroll
    for (int e = 0; e < 8; ++e)
        o[e] = __floats2half2_rn(s[jj][kc + 2 * e], s[jj][kc + 2 * e + 1]);
    __half* dst = g_Wt + (size_t)((j0 + jj) * 4 + gate) * KDIM + k0 + kc;
    reinterpret_cast<uint4*>(dst)[0] = reinterpret_cast<const uint4*>(o)[0];
    reinterpret_cast<uint4*>(dst)[1] = reinterpret_cast<const uint4*>(o)[1];

    if (by == 0 && t < 32) {
        const float* b = (gate == 0) ? bf : (gate == 1) ? bi
                        : (gate == 2) ? bg : bo;
        g_bias[(j0 + t) * 4 + gate] = b[j0 + t];
    }
}

// ---------------------------------------------------------------------------
// Main GEMM + fused LSTM epilogue (256 threads, 8 warps: 4(m) x 2(n))
// GEMM loop identical to R11/R13.
// ---------------------------------------------------------------------------
__global__ __launch_bounds__(256, 2)
void lstm_gemm_kernel(const float* __restrict__ c_in, float* __restrict__ out) {
    extern __shared__ char smem[];
    const uint32_t smem_u32 = smem_to_u32(smem);
    const int tid = threadIdx.x;
    const int wid = tid >> 5;
    const int lane = tid & 31;
    const int warp_m = wid & 3;       // 0..3 -> 32 rows each
    const int warp_n = wid >> 2;      // 0..1 -> 64 cols each
    const int m0 = blockIdx.y * BM;
    const int r0 = blockIdx.x * BN;   // gate-interleaved column base
    const int jb = blockIdx.x * 32;   // hidden-unit base

    float* bias_s = reinterpret_cast<float*>(smem + SMEM_BIAS);
    if (tid < 128) bias_s[tid] = g_bias[r0 + tid];

    // --- producers: single base pointer + compile-time strides -------------
    const int ci = tid & 7;           // 16B chunk in a 128B row
    const int crb = tid >> 3;         // row base (0..31)
    const uint32_t sw0 = (uint32_t)(crb * 128 + ((ci ^ (crb & 7)) << 4));
    const __half* pA0 = g_A  + (size_t)(m0 + crb) * KDIM + ci * 8;
    const __half* pB0 = g_Wt + (size_t)(r0 + crb) * KDIM + ci * 8;

    auto load_stage_adv = [&](uint32_t sm) {
        const uint32_t s0 = sm + sw0;
        #pragma unroll
        for (int rep = 0; rep < 4; ++rep)
            cp_async_16(s0 + rep * 4096, pA0 + rep * ROWSTEP);
        #pragma unroll
        for (int rep = 0; rep < 4; ++rep)
            cp_async_16(s0 + BM * 128 + rep * 4096, pB0 + rep * ROWSTEP);
        pA0 += BK;
        pB0 += BK;
    };

    // prologue: stages 0,1 (groups #0, #1)
    load_stage_adv(smem_u32);
    CP_COMMIT();
    load_stage_adv(smem_u32 + STAGE_BYTES);
    CP_COMMIT();

    float acc[2][8][4];
    #pragma unroll
    for (int mt = 0; mt < 2; ++mt)
        #pragma unroll
        for (int nt = 0; nt < 8; ++nt)
            #pragma unroll
            for (int e = 0; e < 4; ++e) acc[mt][nt][e] = 0.0f;

    const int lrow = lane & 15;
    const int lhalf = lane >> 4;

    const int arow = warp_m * 32 + lrow;
    const int brow = warp_n * 64 + lrow;
    const uint32_t rA0 = (uint32_t)(arow * 128 + ((arow & 7) << 4));
    const uint32_t rB0 = (uint32_t)(brow * 128 + ((brow & 7) << 4));

    uint32_t scBase = smem_u32;                      // stage 0
    uint32_t spBase = smem_u32 + 2 * STAGE_BYTES;    // stage 2
    const uint32_t smTop = smem_u32 + 2 * STAGE_BYTES;

    #pragma unroll 1
    for (int c = 0; c < NCHUNK; ++c) {
        CP_WAIT(1);
        __syncthreads();
        if (c + 2 < NCHUNK)
            load_stage_adv(spBase);
        CP_COMMIT();

        const uint32_t aBase = scBase + rA0;
        const uint32_t bBase = scBase + BM * 128 + rB0;

        #pragma unroll
        for (int ks = 0; ks < 4; ++ks) {
            const uint32_t cx = (uint32_t)((ks * 2 + lhalf) << 4);
            const uint32_t a0 = aBase ^ cx;
            const uint32_t b0 = bBase ^ cx;
            uint32_t a[2][4];
            ldmatrix_x4(a[0][0], a[0][1], a[0][2], a[0][3], a0);
            ldmatrix_x4(a[1][0], a[1][1], a[1][2], a[1][3], a0 + 2048);
            uint32_t b[4][4];
            ldmatrix_x4(b[0][0], b[0][1], b[0][2], b[0][3], b0);
            ldmatrix_x4(b[1][0], b[1][1], b[1][2], b[1][3], b0 + 2048);
            ldmatrix_x4(b[2][0], b[2][1], b[2][2], b[2][3], b0 + 4096);
            ldmatrix_x4(b[3][0], b[3][1], b[3][2], b[3][3], b0 + 6144);
            #pragma unroll
            for (int mt = 0; mt < 2; ++mt)
                #pragma unroll
                for (int nt = 0; nt < 8; ++nt)
                    mma_fp16(acc[mt][nt], a[mt],
                             b[nt >> 1][nt & 1], b[nt >> 1][(nt & 1) + 2]);
        }

        scBase = (scBase == smTop) ? smem_u32 : scBase + STAGE_BYTES;
        spBase = (spBase == smTop) ? smem_u32 : spBase + STAGE_BYTES;
    }

    // ---------------- epilogue: stage z through smem, fuse LSTM ----------------
    CP_WAIT(0);
    __syncthreads();
    float* zbuf = reinterpret_cast<float*>(smem);
    {
        const int rb = warp_m * 32 + (lane >> 2);
        const int cb = warp_n * 64 + (lane & 3) * 2;
        #pragma unroll
        for (int mt = 0; mt < 2; ++mt)
            #pragma unroll
            for (int nt = 0; nt < 8; ++nt) {
                const int r = rb + mt * 16;
                const int cc = cb + nt * 8;
                zbuf[r * ZSTRIDE + cc]           = acc[mt][nt][0];
                zbuf[r * ZSTRIDE + cc + 1]       = acc[mt][nt][1];
                zbuf[(r + 8) * ZSTRIDE + cc]     = acc[mt][nt][2];
                zbuf[(r + 8) * ZSTRIDE + cc + 1] = acc[mt][nt][3];
            }
    }
    __syncthreads();

    {
        const int r = tid >> 1;                 // 0..127 local row
        const int jh = (tid & 1) * 16;          // 16 hidden units per thread
        const size_t m = (size_t)(m0 + r);
        const float* cin = c_in + m * HDIM + jb;
        float* hout = out + m * HDIM + jb;
        float* cout = out + (size_t)MDIM * HDIM + m * HDIM + jb;
        const float* zrow = zbuf + r * ZSTRIDE;

        #pragma unroll
        for (int q = 0; q < 4; ++q) {
            const int j0 = jh + q * 4;
            float4 ci4 = *reinterpret_cast<const float4*>(cin + j0);
            const float* cip = &ci4.x;
            float hv[4], cv[4];
            #pragma unroll
            for (int e = 0; e < 4; ++e) {
                const int j = j0 + e;
                float4 z4 = *reinterpret_cast<const float4*>(zrow + j * 4);
                float4 b4 = *reinterpret_cast<const float4*>(bias_s + j * 4);
                float f = fast_sigmoid(z4.x + b4.x);
                float i = fast_sigmoid(z4.y + b4.y);
                float g = fast_tanh(z4.z + b4.z);
                float o = fast_sigmoid(z4.w + b4.w);
                float cval = f * cip[e] + g * i;
                cv[e] = cval;
                hv[e] = fast_tanh(cval) * o;
            }
            *reinterpret_cast<float4*>(hout + j0) =
                make_float4(hv[0], hv[1], hv[2], hv[3]);
            *reinterpret_cast<float4*>(cout + j0) =
                make_float4(cv[0], cv[1], cv[2], cv[3]);
        }
    }
}

// ---------------------------------------------------------------------------
// kernel_launch
// ---------------------------------------------------------------------------
extern "C" void kernel_launch(void* const* d_in, const int* in_sizes, int n_in,
                              void* d_out, int out_size) {
    const float* x    = (const float*)d_in[0];
    const float* h_in = (const float*)d_in[1];
    const float* c_in = (const float*)d_in[2];
    const float* Wf   = (const float*)d_in[3];
    const float* bf   = (const float*)d_in[4];
    const float* Wi   = (const float*)d_in[5];
    const float* bi   = (const float*)d_in[6];
    const float* Wg   = (const float*)d_in[7];
    const float* bg   = (const float*)d_in[8];
    const float* Wo   = (const float*)d_in[9];
    const float* bo   = (const float*)d_in[10];
    float* out = (float*)d_out;

    prep_kernel<<<PREP_BLOCKS, 256>>>(x, h_in, Wf, Wi, Wg, Wo, bf, bi, bg, bo);

    cudaFuncSetAttribute(lstm_gemm_kernel,
                         cudaFuncAttributeMaxDynamicSharedMemorySize, SMEM_TOTAL);
    lstm_gemm_kernel<<<dim3(NDIM / BN, MDIM / BM), 256, SMEM_TOTAL>>>(c_in, out);
}